// round 14
// baseline (speedup 1.0000x reference)
#include <cuda_runtime.h>
#include <cstdint>

#define FULL 0xffffffffu
typedef unsigned long long u64;

constexpr int Bn = 128;      // batch
constexpr int Sn = 512;      // seq len
constexpr int Dk = 1024;     // feature dim
constexpr int Ln = 50;       // real labels
constexpr int NL = 52;       // labels + START + END
constexpr int STARTL = 50;
constexpr int ENDL = 51;
constexpr float NEGV = -100.0f;
constexpr float LOG2E = 1.4426950408889634f;
constexpr float LN2   = 0.6931471805599453f;

// ---- mma.sync GEMM config (measured 70us) ----
constexpr int TM  = 256;           // rows per CTA
constexpr int KCH = 32;            // k per chunk
constexpr int NCH = Dk / KCH;      // 32 chunks
constexpr int KP  = 36;            // padded k stride (floats)
constexpr int ASZ = TM * KP;       // floats per A buffer (9216)
constexpr int BSZ = 64 * KP;       // floats per B buffer (2304)
constexpr int SMEM_BYTES = (2 * ASZ + 2 * BSZ) * 4;   // 92160

// Scratch (device globals — no allocation allowed)
__device__ float g_logits[(size_t)Bn * Sn * Ln];   // 13.1 MB
__device__ float g_partial[Bn];

// ---------------- PTX helpers ----------------
__device__ __forceinline__ unsigned smem_u32(const void* p) {
    unsigned a;
    asm("{ .reg .u64 t; cvta.to.shared.u64 t, %1; cvt.u32.u64 %0, t; }"
        : "=r"(a) : "l"(p));
    return a;
}
__device__ __forceinline__ void cp16(unsigned dst, const void* src) {
    asm volatile("cp.async.cg.shared.global [%0], [%1], 16;"
                 :: "r"(dst), "l"(src) : "memory");
}
__device__ __forceinline__ void cp_commit() {
    asm volatile("cp.async.commit_group;" ::: "memory");
}
template <int N>
__device__ __forceinline__ void cp_wait() {
    asm volatile("cp.async.wait_group %0;" :: "n"(N) : "memory");
}
__device__ __forceinline__ void mma_tf32(float* c, const unsigned* a,
                                         unsigned b0, unsigned b1) {
    asm volatile(
        "mma.sync.aligned.m16n8k8.row.col.f32.tf32.tf32.f32 "
        "{%0,%1,%2,%3}, {%4,%5,%6,%7}, {%8,%9}, {%0,%1,%2,%3};"
        : "+f"(c[0]), "+f"(c[1]), "+f"(c[2]), "+f"(c[3])
        : "r"(a[0]), "r"(a[1]), "r"(a[2]), "r"(a[3]), "r"(b0), "r"(b1));
}
__device__ __forceinline__ u64 packlh(float lo, float hi) {
    return (u64)__float_as_uint(lo) | ((u64)__float_as_uint(hi) << 32);
}
__device__ __forceinline__ void fma2(u64& d, u64 a, u64 b) {
    asm("fma.rn.f32x2 %0, %1, %2, %0;" : "+l"(d) : "l"(a), "l"(b));
}
__device__ __forceinline__ u64 add2(u64 a, u64 b) {
    u64 d;
    asm("add.rn.f32x2 %0, %1, %2;" : "=l"(d) : "l"(a), "l"(b));
    return d;
}
__device__ __forceinline__ float ex2(float x) {
    float y; asm("ex2.approx.f32 %0, %1;" : "=f"(y) : "f"(x)); return y;
}
__device__ __forceinline__ float lg2(float x) {
    float y; asm("lg2.approx.f32 %0, %1;" : "=f"(y) : "f"(x)); return y;
}
__device__ __forceinline__ float rcp(float x) {
    float y; asm("rcp.approx.f32 %0, %1;" : "=f"(y) : "f"(x)); return y;
}

// ---------------------------------------------------------------------------
// Kernel 1: logits = inputs @ W^T + b  via tf32 mma.sync (m16n8k8).
// (unchanged: measured 70us, tensor 27%, DRAM 24%)
// ---------------------------------------------------------------------------
__global__ void __launch_bounds__(256, 2) gemm_kernel(
    const float* __restrict__ A,     // [B*S, D]
    const float* __restrict__ W,     // [50, D]
    const float* __restrict__ bias,  // [50]
    const int*   __restrict__ lens)  // [B]
{
    extern __shared__ __align__(16) float smem[];
    float* As = smem;                // [2][TM][KP]
    float* Bs = smem + 2 * ASZ;      // [2][64][KP]

    const int blk = blockIdx.x;          // 0..255
    const int bb  = blk >> 1;            // batch
    const int st  = (blk & 1) << 8;      // s-tile start (0 or 256)
    const int len = lens[bb];
    if (st >= len) return;               // fully-masked tile
    const int maxrow = len - st;

    const int tid  = threadIdx.x;
    const int w    = tid >> 5;
    const int lane = tid & 31;
    const int gr   = lane >> 2;
    const int tg   = lane & 3;
    const int row0 = bb * Sn + st;

    const unsigned sbase = smem_u32(smem);
    const unsigned aoff[2] = {sbase, sbase + ASZ * 4};
    const unsigned boff[2] = {sbase + 2 * ASZ * 4, sbase + 2 * ASZ * 4 + BSZ * 4};

    auto stage = [&](int c) {
        const int kc = c * KCH;
        const int buf = c & 1;
#pragma unroll
        for (int i = 0; i < 8; i++) {
            int slot = tid + i * 256;
            int row = slot >> 3, j = slot & 7;
            if (row < maxrow)
                cp16(aoff[buf] + (unsigned)(row * KP + 4 * j) * 4,
                     A + (size_t)(row0 + row) * Dk + kc + 4 * j);
        }
#pragma unroll
        for (int i = 0; i < 2; i++) {
            int slot = tid + i * 256;
            int row = slot >> 3, j = slot & 7;
            if (row < Ln)
                cp16(boff[buf] + (unsigned)(row * KP + 4 * j) * 4,
                     W + (size_t)row * Dk + kc + 4 * j);
        }
        cp_commit();
    };

    float acc[2][8][4];
#pragma unroll
    for (int p = 0; p < 2; p++)
#pragma unroll
        for (int q = 0; q < 8; q++)
#pragma unroll
            for (int r = 0; r < 4; r++) acc[p][q][r] = 0.f;

    stage(0);
    stage(1);

    for (int c = 0; c < NCH; c++) {
        if (c + 1 < NCH) cp_wait<1>(); else cp_wait<0>();
        __syncthreads();

        const int buf = c & 1;
        const float* Ab = As + buf * ASZ + (32 * w + gr) * KP;
        const float* Bb = Bs + buf * BSZ + gr * KP;
#pragma unroll
        for (int s = 0; s < 4; s++) {
            const int k = 8 * s + tg;
            unsigned a[2][4];
#pragma unroll
            for (int p = 0; p < 2; p++) {
                const float* ap = Ab + 16 * p * KP;
                a[p][0] = __float_as_uint(ap[k]);
                a[p][1] = __float_as_uint(ap[8 * KP + k]);
                a[p][2] = __float_as_uint(ap[k + 4]);
                a[p][3] = __float_as_uint(ap[8 * KP + k + 4]);
            }
#pragma unroll
            for (int q = 0; q < 8; q++) {
                unsigned b0 = __float_as_uint(Bb[8 * q * KP + k]);
                unsigned b1 = __float_as_uint(Bb[8 * q * KP + k + 4]);
                mma_tf32(acc[0][q], a[0], b0, b1);
                mma_tf32(acc[1][q], a[1], b0, b1);
            }
        }
        __syncthreads();
        if (c + 2 < NCH) stage(c + 2);
    }

#pragma unroll
    for (int q = 0; q < 8; q++) {
        const int n = 8 * q + 2 * tg;
        if (n < 49) {
            const float b0v = bias[n], b1v = bias[n + 1];
#pragma unroll
            for (int p = 0; p < 2; p++) {
                const int rg = row0 + 32 * w + 16 * p + gr;
                float2 v0 = make_float2(acc[p][q][0] + b0v, acc[p][q][1] + b1v);
                float2 v1 = make_float2(acc[p][q][2] + b0v, acc[p][q][3] + b1v);
                *reinterpret_cast<float2*>(g_logits + (size_t)rg * Ln + n) = v0;
                *reinterpret_cast<float2*>(g_logits + (size_t)(rg + 8) * Ln + n) = v1;
            }
        }
    }
}

// ---------------------------------------------------------------------------
// Kernel 2: CRF forward scan + gold, one 64-thread block per batch.
// LINEAR-domain recurrence: u_i = 2^(R_i - c2). Per step:
//   u_new = (sum_j eT[i][j] * u_j) * (ex2(logit*log2e) * rcp(u0))
// ex2 precomputed in the depth-4 prefetch ring; rcp + lg2(u0) off-chain.
// Critical path: STS -> BAR -> LDS -> fma2 tree -> FMUL. No MUFU in chain.
// ---------------------------------------------------------------------------
__global__ void __launch_bounds__(64) scan_kernel(
    const float* __restrict__ T,      // [52,52], T[i][j] = trans to i from j
    const int*   __restrict__ lens,
    const int*   __restrict__ labels)
{
    __shared__ __align__(16) float es[2][64];
    __shared__ float redm[2], reds[2];
    __shared__ float snorm;

    const int b    = blockIdx.x;
    const int tid  = threadIdx.x;            // 0..63
    const int warp = tid >> 5;
    const int lane = tid & 31;
    const int i    = warp * 26 + lane;       // destination label
    const bool valid    = (lane < 26);
    const bool hasLogit = valid && (i < Ln);
    const int len = lens[b];
    const float* lg = g_logits + (size_t)b * Sn * Ln;
    const float* Trow = T + (valid ? i : 0) * NL;

    // packed exp(transition) row: 26 u64 = 52 regs
    u64 eTp[26];
#pragma unroll
    for (int q = 0; q < 26; q++) {
        float e0 = valid ? __expf(Trow[2 * q])     : 0.f;
        float e1 = valid ? __expf(Trow[2 * q + 1]) : 0.f;
        eTp[q] = packlh(e0, e1);
    }

    // init: u = 2^R0, c2 = 0.  Dead labels (START/END rows are NEG) -> u ~ 0.
    float u = 0.f;
    if (valid)
        u = ex2((Trow[STARTL] + (hasLogit ? lg[i] : NEGV)) * LOG2E);
    float c2 = 0.f;

    // multiplier prefetch ring, depth 4: p = 2^(logit * log2e)
    float p0 = 0.f, p1 = 0.f, p2 = 0.f, p3 = 0.f;
    if (1 < len) p0 = ex2((hasLogit ? lg[Ln + i]     : NEGV) * LOG2E);
    if (2 < len) p1 = ex2((hasLogit ? lg[2 * Ln + i] : NEGV) * LOG2E);
    if (3 < len) p2 = ex2((hasLogit ? lg[3 * Ln + i] : NEGV) * LOG2E);
    if (4 < len) p3 = ex2((hasLogit ? lg[4 * Ln + i] : NEGV) * LOG2E);

    for (int t = 1; t < len; t++) {
        if (valid) es[t & 1][i] = u;
        __syncthreads();
        const float* eb = es[t & 1];

        u64 a0 = 0ull, a1 = 0ull, a2 = 0ull, a3 = 0ull;
        float u0 = 0.f;
#pragma unroll
        for (int q = 0; q < 13; q++) {
            ulonglong2 ev = *reinterpret_cast<const ulonglong2*>(&eb[4 * q]);
            if (q == 0) u0 = __uint_as_float((unsigned)ev.x);
            if (q & 1) { fma2(a0, eTp[2 * q], ev.x); fma2(a1, eTp[2 * q + 1], ev.y); }
            else       { fma2(a2, eTp[2 * q], ev.x); fma2(a3, eTp[2 * q + 1], ev.y); }
        }
        const float rc = rcp(u0);               // off-chain: ready before tree ends
        u64 tot = add2(add2(a0, a1), add2(a2, a3));
        float s = __uint_as_float((unsigned)tot) +
                  __uint_as_float((unsigned)(tot >> 32));

        u = s * (p0 * rc);                      // only FMULs on the chain
        c2 += lg2(u0);                          // off-chain offset accumulation

        p0 = p1; p1 = p2; p2 = p3;
        const int tn = t + 4;
        if (tn < len)
            p3 = ex2((hasLogit ? lg[tn * Ln + i] : NEGV) * LOG2E);
    }

    // norm = ln2 * (c2 + LSE2_i(lg2(u_i) + T[END][i]*log2e))
    float v2 = (valid && u > 0.f) ? (lg2(u) + T[ENDL * NL + i] * LOG2E) : -1e30f;
    float m2 = v2;
#pragma unroll
    for (int o = 16; o; o >>= 1) m2 = fmaxf(m2, __shfl_xor_sync(FULL, m2, o));
    if (lane == 0) redm[warp] = m2;
    __syncthreads();
    m2 = fmaxf(redm[0], redm[1]);
    float sx = (v2 > -1e29f) ? ex2(v2 - m2) : 0.f;
#pragma unroll
    for (int o = 16; o; o >>= 1) sx += __shfl_xor_sync(FULL, sx, o);
    if (lane == 0) reds[warp] = sx;
    __syncthreads();
    if (tid == 0) snorm = LN2 * (c2 + m2 + lg2(reds[0] + reds[1]));

    // ---- gold score (natural domain, exact inputs) ----
    const int* lab = labels + b * Sn;
    float gs = 0.f;
    for (int t = tid; t < len; t += 64) {
        int lt = lab[t];
        int prev = (t == 0) ? STARTL : lab[t - 1];
        gs += lg[t * Ln + lt] + T[lt * NL + prev];
    }
    if (tid == 0) gs += T[ENDL * NL + lab[len - 1]];
#pragma unroll
    for (int o = 16; o; o >>= 1) gs += __shfl_xor_sync(FULL, gs, o);
    __syncthreads();
    if (lane == 0) redm[warp] = gs;
    __syncthreads();
    if (tid == 0) g_partial[b] = (redm[0] + redm[1]) - snorm;
}

// ---------------------------------------------------------------------------
// Kernel 3: loss = -sum_b partial[b]
// ---------------------------------------------------------------------------
__global__ void __launch_bounds__(128) finalize_kernel(float* __restrict__ out)
{
    const int tid = threadIdx.x;
    float v = g_partial[tid];
#pragma unroll
    for (int o = 16; o; o >>= 1) v += __shfl_xor_sync(FULL, v, o);
    __shared__ float red[4];
    if ((tid & 31) == 0) red[tid >> 5] = v;
    __syncthreads();
    if (tid == 0) {
        out[0] = -((red[0] + red[1]) + (red[2] + red[3]));
    }
}

// ---------------------------------------------------------------------------
extern "C" void kernel_launch(void* const* d_in, const int* in_sizes, int n_in,
                              void* d_out, int out_size)
{
    const float* inputs  = (const float*)d_in[0];   // [128,512,1024]
    const float* W       = (const float*)d_in[1];   // [50,1024]
    const float* bias    = (const float*)d_in[2];   // [50]
    const float* T       = (const float*)d_in[3];   // [52,52]
    const int*   lens    = (const int*)  d_in[4];   // [128]
    const int*   labels  = (const int*)  d_in[5];   // [128,512]
    float* out = (float*)d_out;

    static bool attr_set = false;
    if (!attr_set) {
        cudaFuncSetAttribute(gemm_kernel,
                             cudaFuncAttributeMaxDynamicSharedMemorySize,
                             SMEM_BYTES);
        attr_set = true;
    }

    gemm_kernel<<<Bn * (Sn / TM), 256, SMEM_BYTES>>>(inputs, W, bias, lens);
    scan_kernel<<<Bn, 64>>>(T, lens, labels);
    finalize_kernel<<<1, 128>>>(out);
}

// round 15
// speedup vs baseline: 1.4439x; 1.4439x over previous
#include <cuda_runtime.h>
#include <cstdint>

#define FULL 0xffffffffu
typedef unsigned long long u64;

constexpr int Bn = 128;      // batch
constexpr int Sn = 512;      // seq len
constexpr int Dk = 1024;     // feature dim
constexpr int Ln = 50;       // real labels
constexpr int NL = 52;       // labels + START + END
constexpr int STARTL = 50;
constexpr int ENDL = 51;
constexpr float NEGV = -100.0f;

// ---- mma.sync GEMM config: TM=128, 3 CTAs/SM ----
constexpr int TM  = 128;           // rows per CTA
constexpr int KCH = 32;            // k per chunk
constexpr int NCH = Dk / KCH;      // 32 chunks
constexpr int KP  = 36;            // padded k stride (floats)
constexpr int ASZ = TM * KP;       // floats per A buffer (4608)
constexpr int BSZ = 64 * KP;       // floats per B buffer (2304)
constexpr int SMEM_BYTES = (2 * ASZ + 2 * BSZ) * 4;   // 55296

// Scratch (device globals — no allocation allowed)
__device__ float g_logits[(size_t)Bn * Sn * Ln];   // 13.1 MB
__device__ float g_partial[Bn];

// ---------------- PTX helpers ----------------
__device__ __forceinline__ unsigned smem_u32(const void* p) {
    unsigned a;
    asm("{ .reg .u64 t; cvta.to.shared.u64 t, %1; cvt.u32.u64 %0, t; }"
        : "=r"(a) : "l"(p));
    return a;
}
__device__ __forceinline__ void cp16(unsigned dst, const void* src) {
    asm volatile("cp.async.cg.shared.global [%0], [%1], 16;"
                 :: "r"(dst), "l"(src) : "memory");
}
__device__ __forceinline__ void cp_commit() {
    asm volatile("cp.async.commit_group;" ::: "memory");
}
template <int N>
__device__ __forceinline__ void cp_wait() {
    asm volatile("cp.async.wait_group %0;" :: "n"(N) : "memory");
}
__device__ __forceinline__ void mma_tf32(float* c, const unsigned* a,
                                         unsigned b0, unsigned b1) {
    asm volatile(
        "mma.sync.aligned.m16n8k8.row.col.f32.tf32.tf32.f32 "
        "{%0,%1,%2,%3}, {%4,%5,%6,%7}, {%8,%9}, {%0,%1,%2,%3};"
        : "+f"(c[0]), "+f"(c[1]), "+f"(c[2]), "+f"(c[3])
        : "r"(a[0]), "r"(a[1]), "r"(a[2]), "r"(a[3]), "r"(b0), "r"(b1));
}
__device__ __forceinline__ u64 packlh(float lo, float hi) {
    return (u64)__float_as_uint(lo) | ((u64)__float_as_uint(hi) << 32);
}
__device__ __forceinline__ void fma2(u64& d, u64 a, u64 b) {
    asm("fma.rn.f32x2 %0, %1, %2, %0;" : "+l"(d) : "l"(a), "l"(b));
}
__device__ __forceinline__ u64 add2(u64 a, u64 b) {
    u64 d;
    asm("add.rn.f32x2 %0, %1, %2;" : "=l"(d) : "l"(a), "l"(b));
    return d;
}

// ---------------------------------------------------------------------------
// Kernel 1: logits = inputs @ W^T + b  via tf32 mma.sync (m16n8k8).
// TM=128: 8 warps x 16 rows, acc 32 regs/thread -> 3 CTAs/SM (occ ~37%).
// cp.async double-buffered K chunks; per-row len masking on loads;
// fully-masked tiles exit early (~37% at this tile size).
// ---------------------------------------------------------------------------
__global__ void __launch_bounds__(256, 3) gemm_kernel(
    const float* __restrict__ A,     // [B*S, D]
    const float* __restrict__ W,     // [50, D]
    const float* __restrict__ bias,  // [50]
    const int*   __restrict__ lens)  // [B]
{
    extern __shared__ __align__(16) float smem[];
    float* As = smem;                // [2][TM][KP]
    float* Bs = smem + 2 * ASZ;      // [2][64][KP]

    const int blk = blockIdx.x;          // 0..511
    const int bb  = blk >> 2;            // batch
    const int st  = (blk & 3) << 7;      // s-tile start (0,128,256,384)
    const int len = lens[bb];
    if (st >= len) return;               // fully-masked tile
    const int maxrow = min(TM, len - st);

    const int tid  = threadIdx.x;
    const int w    = tid >> 5;
    const int lane = tid & 31;
    const int gr   = lane >> 2;          // groupID
    const int tg   = lane & 3;           // thread-in-group
    const int row0 = bb * Sn + st;

    const unsigned sbase = smem_u32(smem);
    const unsigned aoff[2] = {sbase, sbase + ASZ * 4};
    const unsigned boff[2] = {sbase + 2 * ASZ * 4, sbase + 2 * ASZ * 4 + BSZ * 4};

    auto stage = [&](int c) {
        const int kc = c * KCH;
        const int buf = c & 1;
#pragma unroll
        for (int i = 0; i < 4; i++) {
            int slot = tid + i * 256;        // 0..1023
            int row = slot >> 3, j = slot & 7;
            if (row < maxrow)
                cp16(aoff[buf] + (unsigned)(row * KP + 4 * j) * 4,
                     A + (size_t)(row0 + row) * Dk + kc + 4 * j);
        }
#pragma unroll
        for (int i = 0; i < 2; i++) {
            int slot = tid + i * 256;        // 0..511
            int row = slot >> 3, j = slot & 7;
            if (row < Ln)
                cp16(boff[buf] + (unsigned)(row * KP + 4 * j) * 4,
                     W + (size_t)row * Dk + kc + 4 * j);
        }
        cp_commit();
    };

    float acc[8][4];
#pragma unroll
    for (int q = 0; q < 8; q++)
#pragma unroll
        for (int r = 0; r < 4; r++) acc[q][r] = 0.f;

    stage(0);
    stage(1);

    for (int c = 0; c < NCH; c++) {
        if (c + 1 < NCH) cp_wait<1>(); else cp_wait<0>();
        __syncthreads();

        const int buf = c & 1;
        const float* Ab = As + buf * ASZ + (16 * w + gr) * KP;
        const float* Bb = Bs + buf * BSZ + gr * KP;
#pragma unroll
        for (int s = 0; s < 4; s++) {
            const int k = 8 * s + tg;
            unsigned a[4];
            a[0] = __float_as_uint(Ab[k]);
            a[1] = __float_as_uint(Ab[8 * KP + k]);
            a[2] = __float_as_uint(Ab[k + 4]);
            a[3] = __float_as_uint(Ab[8 * KP + k + 4]);
#pragma unroll
            for (int q = 0; q < 8; q++) {
                unsigned b0 = __float_as_uint(Bb[8 * q * KP + k]);
                unsigned b1 = __float_as_uint(Bb[8 * q * KP + k + 4]);
                mma_tf32(acc[q], a, b0, b1);
            }
        }
        __syncthreads();
        if (c + 2 < NCH) stage(c + 2);
    }

    // ---- epilogue: + bias, direct float2 stores ----
#pragma unroll
    for (int q = 0; q < 8; q++) {
        const int n = 8 * q + 2 * tg;
        if (n < 49) {
            const float b0v = bias[n], b1v = bias[n + 1];
            const int rg = row0 + 16 * w + gr;
            float2 v0 = make_float2(acc[q][0] + b0v, acc[q][1] + b1v);
            float2 v1 = make_float2(acc[q][2] + b0v, acc[q][3] + b1v);
            *reinterpret_cast<float2*>(g_logits + (size_t)rg * Ln + n) = v0;
            *reinterpret_cast<float2*>(g_logits + (size_t)(rg + 8) * Ln + n) = v1;
        }
    }
}

// ---------------------------------------------------------------------------
// Kernel 2: CRF forward scan + gold, one 64-thread block per batch.
// R11-exact (best measured: ~130us inside the 207us run): natural-log
// domain, depth-2 logit prefetch, one __syncthreads per step,
// stale-by-one renorm constant off the critical path.
// ---------------------------------------------------------------------------
__global__ void __launch_bounds__(64) scan_kernel(
    const float* __restrict__ T,      // [52,52], T[i][j] = trans to i from j
    const int*   __restrict__ lens,
    const int*   __restrict__ labels)
{
    __shared__ __align__(16) float es[2][64];
    __shared__ float redm[2], reds[2];
    __shared__ float snorm;

    const int b    = blockIdx.x;
    const int tid  = threadIdx.x;            // 0..63
    const int warp = tid >> 5;
    const int lane = tid & 31;
    const int i    = warp * 26 + lane;       // destination label
    const bool valid    = (lane < 26);
    const bool hasLogit = valid && (i < Ln);
    const int len = lens[b];
    const float* lg = g_logits + (size_t)b * Sn * Ln;
    const float* Trow = T + (valid ? i : 0) * NL;

    // packed exp(transition) row: 26 u64 = 52 regs
    u64 eTp[26];
#pragma unroll
    for (int q = 0; q < 26; q++) {
        float e0 = valid ? __expf(Trow[2 * q])     : 0.f;
        float e1 = valid ? __expf(Trow[2 * q + 1]) : 0.f;
        eTp[q] = packlh(e0, e1);
    }

    // t=0: r_i = T[i][START] + logit_0[i]
    float r = valid ? (Trow[STARTL] + (hasLogit ? lg[i] : NEGV)) : -1e30f;
    float off = 0.f, c = 0.f;

    // logit prefetch (depth 2)
    float cur = 0.f, nxt = 0.f;
    if (1 < len) cur = hasLogit ? lg[Ln + i]     : NEGV;
    if (2 < len) nxt = hasLogit ? lg[2 * Ln + i] : NEGV;

    for (int t = 1; t < len; t++) {
        const float u = __expf(r - c);
        if (valid) es[t & 1][i] = u;
        __syncthreads();
        const float* eb = es[t & 1];

        u64 a0 = 0ull, a1 = 0ull, a2 = 0ull, a3 = 0ull;
        float u0 = 0.f;
#pragma unroll
        for (int q = 0; q < 13; q++) {
            ulonglong2 ev = *reinterpret_cast<const ulonglong2*>(&eb[4 * q]);
            if (q == 0) u0 = __uint_as_float((unsigned)ev.x);
            if (q & 1) { fma2(a0, eTp[2 * q], ev.x); fma2(a1, eTp[2 * q + 1], ev.y); }
            else       { fma2(a2, eTp[2 * q], ev.x); fma2(a3, eTp[2 * q + 1], ev.y); }
        }
        u64 tot = add2(add2(a0, a1), add2(a2, a3));
        float s = __uint_as_float((unsigned)tot) +
                  __uint_as_float((unsigned)(tot >> 32));

        r = __logf(s) + cur;                 // dead lanes: log(0) = -inf
        const float cold = c;
        off += cold;
        c = __logf(u0) + cold;               // stale-by-one renorm constant

        cur = nxt;
        const int tn = t + 2;
        if (tn < len) nxt = hasLogit ? lg[tn * Ln + i] : NEGV;
    }

    // norm_score = off + LSE_i(r_i + T[END][i])
    float v = valid ? (r + T[ENDL * NL + i]) : -1e30f;
    float m = v;
#pragma unroll
    for (int o = 16; o; o >>= 1) m = fmaxf(m, __shfl_xor_sync(FULL, m, o));
    if (lane == 0) redm[warp] = m;
    __syncthreads();
    m = fmaxf(redm[0], redm[1]);
    float sx = (valid && v > -1e29f) ? __expf(v - m) : 0.f;
#pragma unroll
    for (int o = 16; o; o >>= 1) sx += __shfl_xor_sync(FULL, sx, o);
    if (lane == 0) reds[warp] = sx;
    __syncthreads();
    if (tid == 0) snorm = off + m + __logf(reds[0] + reds[1]);

    // ---- gold score (fused) ----
    const int* lab = labels + b * Sn;
    float gs = 0.f;
    for (int t = tid; t < len; t += 64) {
        int lt = lab[t];
        int prev = (t == 0) ? STARTL : lab[t - 1];
        gs += lg[t * Ln + lt] + T[lt * NL + prev];
    }
    if (tid == 0) gs += T[ENDL * NL + lab[len - 1]];
#pragma unroll
    for (int o = 16; o; o >>= 1) gs += __shfl_xor_sync(FULL, gs, o);
    __syncthreads();
    if (lane == 0) redm[warp] = gs;
    __syncthreads();
    if (tid == 0) g_partial[b] = (redm[0] + redm[1]) - snorm;
}

// ---------------------------------------------------------------------------
// Kernel 3: loss = -sum_b partial[b]
// ---------------------------------------------------------------------------
__global__ void __launch_bounds__(128) finalize_kernel(float* __restrict__ out)
{
    const int tid = threadIdx.x;
    float v = g_partial[tid];
#pragma unroll
    for (int o = 16; o; o >>= 1) v += __shfl_xor_sync(FULL, v, o);
    __shared__ float red[4];
    if ((tid & 31) == 0) red[tid >> 5] = v;
    __syncthreads();
    if (tid == 0) {
        out[0] = -((red[0] + red[1]) + (red[2] + red[3]));
    }
}

// ---------------------------------------------------------------------------
extern "C" void kernel_launch(void* const* d_in, const int* in_sizes, int n_in,
                              void* d_out, int out_size)
{
    const float* inputs  = (const float*)d_in[0];   // [128,512,1024]
    const float* W       = (const float*)d_in[1];   // [50,1024]
    const float* bias    = (const float*)d_in[2];   // [50]
    const float* T       = (const float*)d_in[3];   // [52,52]
    const int*   lens    = (const int*)  d_in[4];   // [128]
    const int*   labels  = (const int*)  d_in[5];   // [128,512]
    float* out = (float*)d_out;

    static bool attr_set = false;
    if (!attr_set) {
        cudaFuncSetAttribute(gemm_kernel,
                             cudaFuncAttributeMaxDynamicSharedMemorySize,
                             SMEM_BYTES);
        attr_set = true;
    }

    gemm_kernel<<<Bn * (Sn / TM), 256, SMEM_BYTES>>>(inputs, W, bias, lens);
    scan_kernel<<<Bn, 64>>>(T, lens, labels);
    finalize_kernel<<<1, 128>>>(out);
}